// round 9
// baseline (speedup 1.0000x reference)
#include <cuda_runtime.h>
#include <stdint.h>

// ---------------------------------------------------------------------------
// ChannelFeatureSNN: T=16 LIF-SNN
//   conv1(2->256,K5,p2) -> LIF -> conv2(256->128,K3,p1) -> LIF
//   -> conv3(128->64,K3,p1) -> LIF -> conv4(64->2,K3,p1) -> LIF
//   -> flatten(256) -> fc1(256->100) -> LIF -> fc2(100->40) accumulated, /T
// Key structure exploited:
//   * conv1 input is time-invariant -> layer-1 spike trains computed in one
//     pass (no mem1 state at all), packed as bit-planes per timestep.
//   * spikes are binary -> stored as bitmasks (1 bit/neuron), expanded to
//     fp32 in smem only inside the conv tiles.
// ---------------------------------------------------------------------------

#define Bsz 2048
#define Lx  128
#define Tst 16
#define C1  256
#define C2  128
#define C3  64

// bit-packed spikes: [t][b][ci][4 x uint32 over l]
__device__ uint32_t g_s1[(size_t)Tst * Bsz * C1 * 4];   // 128 MB
__device__ uint32_t g_s2[(size_t)Bsz * C2 * 4];         // 4 MB (per-step transient)
__device__ uint32_t g_s3[(size_t)Bsz * C3 * 4];         // 2 MB
__device__ float    g_mem2[(size_t)Bsz * C2 * Lx];      // 128 MB
__device__ float    g_mem3[(size_t)Bsz * C3 * Lx];      // 64 MB
__device__ float    g_mem4[(size_t)Bsz * 256];          // 2 MB
__device__ float    g_mem5[(size_t)Bsz * 100];          // 0.8 MB
__device__ float    g_wT2[C1 * 3 * C2];                 // W2 transposed [ci][k][co]
__device__ float    g_wT3[C2 * 3 * C3];                 // W3 transposed [ci][k][co]

// ---------------------------------------------------------------------------
// prep: transpose conv weights to [ci][k][co] so smem staging is coalesced
// ---------------------------------------------------------------------------
__global__ void prep_kernel(const float* __restrict__ W2,
                            const float* __restrict__ W3) {
    int i = blockIdx.x * blockDim.x + threadIdx.x;
    if (i < C1 * 3 * C2) {
        int co = i % C2; int r = i / C2; int k = r % 3; int ci = r / 3;
        g_wT2[i] = W2[(co * C1 + ci) * 3 + k];
    }
    if (i < C2 * 3 * C3) {
        int co = i % C3; int r = i / C3; int k = r % 3; int ci = r / 3;
        g_wT3[i] = W3[(co * C2 + ci) * 3 + k];
    }
}

// ---------------------------------------------------------------------------
// k0: conv1 + full 16-step layer-1 LIF (constant drive), ballot-pack spikes.
// One warp handles (b, co, 32 consecutive l). Grid covers exactly.
// ---------------------------------------------------------------------------
__global__ void k0_kernel(const float* __restrict__ x,
                          const float* __restrict__ W1,
                          const float* __restrict__ b1) {
    int gw   = blockIdx.x * (blockDim.x >> 5) + (threadIdx.x >> 5);
    int lane = threadIdx.x & 31;
    int lchunk = gw & 3;
    int co     = (gw >> 2) & 255;
    int b      = gw >> 10;
    int l = lchunk * 32 + lane;

    float cur = b1[co];
#pragma unroll
    for (int ci = 0; ci < 2; ci++) {
        const float* xr = x + ((size_t)b * 2 + ci) * Lx;
        const float* wr = W1 + (co * 2 + ci) * 5;
#pragma unroll
        for (int k = 0; k < 5; k++) {
            int ll = l + k - 2;
            float xv = (ll >= 0 && ll < Lx) ? xr[ll] : 0.0f;
            cur = fmaf(xv, wr[k], cur);
        }
    }

    float m = 0.0f;
    size_t base = (((size_t)b) * C1 + co) * 4 + lchunk;
#pragma unroll
    for (int t = 0; t < Tst; t++) {
        float r = (m > 1.0f) ? 1.0f : 0.0f;   // reset from PREVIOUS membrane
        m = fmaf(0.9f, m, cur) - r;
        unsigned bal = __ballot_sync(0xffffffffu, m > 1.0f);
        if (lane == 0) g_s1[(size_t)t * Bsz * C1 * 4 + base] = bal;
    }
}

// ---------------------------------------------------------------------------
// convlif<CI,CO>: K=3 pad=1 conv over binary spikes + fused LIF.
// One CTA per batch element: output tile CO x 128. 256 threads; thread owns
// (co = tid%CO, l-range of LT = CO*128/256). Spikes expanded to fp32 in smem
// with halo; inner loop: 1 broadcast LDS + 3 FFMA per (ci,l).
// Output spikes re-packed to bits (thread owns whole 32-bit words).
// ---------------------------------------------------------------------------
template <int CI, int CO>
__global__ void __launch_bounds__(256, 2) convlif_kernel(
    int t,
    const uint32_t* __restrict__ sin,   // [b][ci][4 words]
    uint32_t* __restrict__ sout,        // [b][co][4 words]
    const float* __restrict__ wT,       // [ci][k][co]
    const float* __restrict__ bias,
    float* __restrict__ mem)            // [b][co][l]
{
    constexpr int LT    = (CO * Lx) / 256;
    constexpr int CHUNK = 16;
    __shared__ float sA[CHUNK][Lx + 2];
    __shared__ float wS[CHUNK][3][CO];

    int tid = threadIdx.x;
    int b   = blockIdx.x;
    int co  = tid % CO;
    int lg  = tid / CO;
    int base_l = lg * LT;

    float acc[LT];
#pragma unroll
    for (int i = 0; i < LT; i++) acc[i] = 0.0f;

    const uint32_t* srow = sin + (size_t)b * CI * 4;

    for (int cb = 0; cb < CI; cb += CHUNK) {
        // stage spikes as fp32 with zero halo
        for (int j = tid; j < CHUNK * Lx; j += 256) {
            int ci = j >> 7;
            int l  = j & 127;
            uint32_t w = srow[(cb + ci) * 4 + (l >> 5)];
            sA[ci][l + 1] = ((w >> (l & 31)) & 1u) ? 1.0f : 0.0f;
        }
        if (tid < CHUNK) { sA[tid][0] = 0.0f; sA[tid][Lx + 1] = 0.0f; }
        // stage weights (contiguous thanks to prep transpose)
        const float* wsrc = wT + (size_t)cb * 3 * CO;
        for (int j = tid; j < CHUNK * 3 * CO; j += 256) {
            ((float*)wS)[j] = wsrc[j];
        }
        __syncthreads();

#pragma unroll 1
        for (int ci = 0; ci < CHUNK; ci++) {
            float w0 = wS[ci][0][co];
            float w1 = wS[ci][1][co];
            float w2 = wS[ci][2][co];
            float a  = sA[ci][base_l];        // s[base_l - 1]
            float s0 = sA[ci][base_l + 1];    // s[base_l]
#pragma unroll
            for (int l = 0; l < LT; l++) {
                float c = sA[ci][base_l + l + 2];   // s[base_l + l + 1]
                acc[l] = fmaf(w0, a,  acc[l]);
                acc[l] = fmaf(w1, s0, acc[l]);
                acc[l] = fmaf(w2, c,  acc[l]);
                a = s0; s0 = c;
            }
        }
        __syncthreads();
    }

    // fused LIF epilogue
    float bv = bias[co];
    float* mrow = mem + ((size_t)b * CO + co) * Lx + base_l;
    uint32_t bits[LT / 32];
#pragma unroll
    for (int w = 0; w < LT / 32; w++) bits[w] = 0u;
#pragma unroll
    for (int l = 0; l < LT; l++) {
        float cur = acc[l] + bv;
        float m = (t == 0) ? 0.0f : mrow[l];
        float r = (m > 1.0f) ? 1.0f : 0.0f;
        m = fmaf(0.9f, m, cur) - r;
        mrow[l] = m;
        if (m > 1.0f) bits[l >> 5] |= (1u << (l & 31));
    }
    uint32_t* so = sout + ((size_t)b * CO + co) * 4 + (base_l >> 5);
#pragma unroll
    for (int w = 0; w < LT / 32; w++) so[w] = bits[w];
}

// ---------------------------------------------------------------------------
// k45: conv4(64->2,K3) + LIF4 + fc1(256->100) + LIF5 + fc2(100->40) accum.
// One CTA (128 threads) per batch element.
// flat index = co*128 + l  (reshape of (B,2,128)).
// ---------------------------------------------------------------------------
__global__ void k45_kernel(int t,
                           const float* __restrict__ W4, const float* __restrict__ b4,
                           const float* __restrict__ fw1, const float* __restrict__ fb1,
                           const float* __restrict__ fw2, const float* __restrict__ fb2,
                           float* __restrict__ out) {
    __shared__ uint32_t s3w[C3 * 4];
    __shared__ float    w4s[2 * C3 * 3];
    __shared__ float    s4f[256];
    __shared__ float    s5f[100];

    int tid = threadIdx.x;
    int b   = blockIdx.x;

    for (int j = tid; j < C3 * 4; j += 128)   s3w[j] = g_s3[(size_t)b * C3 * 4 + j];
    for (int j = tid; j < 2 * C3 * 3; j += 128) w4s[j] = W4[j];
    __syncthreads();

    // conv4 + LIF4 : two flat outputs per thread
#pragma unroll
    for (int half = 0; half < 2; half++) {
        int o  = tid + half * 128;
        int co = o >> 7;
        int l  = o & 127;
        float cur = b4[co];
#pragma unroll 1
        for (int ci = 0; ci < C3; ci++) {
            const float* wr = &w4s[(co * C3 + ci) * 3];
#pragma unroll
            for (int k = 0; k < 3; k++) {
                int ll = l + k - 1;
                if (ll >= 0 && ll < Lx) {
                    uint32_t wd = s3w[ci * 4 + (ll >> 5)];
                    if ((wd >> (ll & 31)) & 1u) cur += wr[k];
                }
            }
        }
        float m = (t == 0) ? 0.0f : g_mem4[(size_t)b * 256 + o];
        float r = (m > 1.0f) ? 1.0f : 0.0f;
        m = fmaf(0.9f, m, cur) - r;
        g_mem4[(size_t)b * 256 + o] = m;
        s4f[o] = (m > 1.0f) ? 1.0f : 0.0f;
    }
    __syncthreads();

    // fc1 + LIF5
    if (tid < 100) {
        float cur = fb1[tid];
        const float* wr = fw1 + (size_t)tid * 256;
#pragma unroll 4
        for (int j = 0; j < 256; j++) cur = fmaf(s4f[j], wr[j], cur);
        float m = (t == 0) ? 0.0f : g_mem5[(size_t)b * 100 + tid];
        float r = (m > 1.0f) ? 1.0f : 0.0f;
        m = fmaf(0.9f, m, cur) - r;
        g_mem5[(size_t)b * 100 + tid] = m;
        s5f[tid] = (m > 1.0f) ? 1.0f : 0.0f;
    }
    __syncthreads();

    // fc2 accumulate; finalize at last step: out = fb2 + (sum_t v_t)/T
    if (tid < 40) {
        float v = 0.0f;
        const float* wr = fw2 + (size_t)tid * 100;
#pragma unroll 4
        for (int j = 0; j < 100; j++) v = fmaf(s5f[j], wr[j], v);
        size_t oi = (size_t)b * 40 + tid;
        float sum = (t == 0) ? v : (out[oi] + v);
        out[oi] = (t == Tst - 1) ? (sum * (1.0f / Tst) + fb2[tid]) : sum;
    }
}

// ---------------------------------------------------------------------------
extern "C" void kernel_launch(void* const* d_in, const int* in_sizes, int n_in,
                              void* d_out, int out_size) {
    const float* x   = (const float*)d_in[0];
    const float* W1  = (const float*)d_in[1];
    const float* b1  = (const float*)d_in[2];
    const float* W2  = (const float*)d_in[3];
    const float* b2  = (const float*)d_in[4];
    const float* W3  = (const float*)d_in[5];
    const float* b3  = (const float*)d_in[6];
    const float* W4  = (const float*)d_in[7];
    const float* b4  = (const float*)d_in[8];
    const float* fw1 = (const float*)d_in[9];
    const float* fb1 = (const float*)d_in[10];
    const float* fw2 = (const float*)d_in[11];
    const float* fb2 = (const float*)d_in[12];
    float* out = (float*)d_out;

    void *ps1, *ps2, *ps3, *pm2, *pm3, *pw2, *pw3;
    cudaGetSymbolAddress(&ps1, g_s1);
    cudaGetSymbolAddress(&ps2, g_s2);
    cudaGetSymbolAddress(&ps3, g_s3);
    cudaGetSymbolAddress(&pm2, g_mem2);
    cudaGetSymbolAddress(&pm3, g_mem3);
    cudaGetSymbolAddress(&pw2, g_wT2);
    cudaGetSymbolAddress(&pw3, g_wT3);

    prep_kernel<<<(C1 * 3 * C2 + 255) / 256, 256>>>(W2, W3);

    // conv1 + full layer-1 simulation (one warp per (b,co,l-chunk))
    k0_kernel<<<(Bsz * C1 * 4) / 8, 256>>>(x, W1, b1);

    for (int t = 0; t < Tst; t++) {
        convlif_kernel<C1, C2><<<Bsz, 256>>>(
            t, (const uint32_t*)ps1 + (size_t)t * Bsz * C1 * 4,
            (uint32_t*)ps2, (const float*)pw2, b2, (float*)pm2);
        convlif_kernel<C2, C3><<<Bsz, 256>>>(
            t, (const uint32_t*)ps2,
            (uint32_t*)ps3, (const float*)pw3, b3, (float*)pm3);
        k45_kernel<<<Bsz, 128>>>(t, W4, b4, fw1, fb1, fw2, fb2, out);
    }
}

// round 11
// speedup vs baseline: 2.5119x; 2.5119x over previous
#include <cuda_runtime.h>
#include <cuda_bf16.h>
#include <stdint.h>

#define Bsz 2048
#define Lx  128
#define Tst 16
#define C1  256
#define C2  128
#define C3  64

// spike bit-planes, layout [..][l][ci-words]
__device__ uint32_t g_s1[(size_t)Tst * Bsz * Lx * (C1 / 32)];  // 134 MB
__device__ uint32_t g_s2[(size_t)Bsz * Lx * (C2 / 32)];
__device__ uint32_t g_s3[(size_t)Bsz * Lx * (C3 / 32)];
__device__ float    g_mem2[(size_t)Bsz * Lx * C2];   // [b][l][co]
__device__ float    g_mem3[(size_t)Bsz * Lx * C3];
__device__ float    g_mem4[(size_t)Bsz * 256];
__device__ float    g_mem5[(size_t)Bsz * 100];

// B fragment tables (mma.m16n8k16 lane layout), bi=(k*3+split):
// idx = ((bi*KT + kt)*NT + nt)*64 + lane*2 + r   (uint32)
__device__ __align__(16) uint32_t g_fragB2[9 * 16 * 16 * 64];  // 590 KB
__device__ __align__(16) uint32_t g_fragB3[9 * 8 * 8 * 64];    // 147 KB

// ---------------------------------------------------------------------------
// 3-way bf16 split: w = hi + mid + lo, residual ~2^-24 relative
// ---------------------------------------------------------------------------
__device__ __forceinline__ uint16_t pick_split(float w, int split) {
    __nv_bfloat16 h = __float2bfloat16(w);
    float r1 = w - __bfloat162float(h);
    __nv_bfloat16 m = __float2bfloat16(r1);
    float r2 = r1 - __bfloat162float(m);
    __nv_bfloat16 lo = __float2bfloat16(r2);
    __nv_bfloat16 v = (split == 0) ? h : (split == 1) ? m : lo;
    return __bfloat16_as_ushort(v);
}

// prep: bake B fragments for conv2 / conv3.
// B frag (16x8, col-major view): b_r holds (k=tg*2+r*8, n=g) and (k+1, n=g).
__global__ void prep_kernel(const float* __restrict__ W2,
                            const float* __restrict__ W3) {
    int i = blockIdx.x * blockDim.x + threadIdx.x;
    if (i < 9 * 16 * 16 * 32) {   // conv2: KT=16, NT=16
        int lane = i & 31;
        int nt = (i >> 5) & 15;
        int kt = (i >> 9) & 15;
        int bi = i >> 13;                 // k*3 + split
        int k = bi / 3, split = bi % 3;
        int g = lane >> 2, tg = lane & 3;
        int co = nt * 8 + g;
#pragma unroll
        for (int r = 0; r < 2; r++) {
            int ci0 = kt * 16 + tg * 2 + r * 8;
            uint16_t lo = pick_split(W2[(co * C1 + ci0) * 3 + k], split);
            uint16_t hi = pick_split(W2[(co * C1 + ci0 + 1) * 3 + k], split);
            g_fragB2[i * 2 + r] = (uint32_t)lo | ((uint32_t)hi << 16);
        }
    }
    if (i < 9 * 8 * 8 * 32) {     // conv3: KT=8, NT=8
        int lane = i & 31;
        int nt = (i >> 5) & 7;
        int kt = (i >> 8) & 7;
        int bi = i >> 11;
        int k = bi / 3, split = bi % 3;
        int g = lane >> 2, tg = lane & 3;
        int co = nt * 8 + g;
#pragma unroll
        for (int r = 0; r < 2; r++) {
            int ci0 = kt * 16 + tg * 2 + r * 8;
            uint16_t lo = pick_split(W3[(co * C2 + ci0) * 3 + k], split);
            uint16_t hi = pick_split(W3[(co * C2 + ci0 + 1) * 3 + k], split);
            g_fragB3[i * 2 + r] = (uint32_t)lo | ((uint32_t)hi << 16);
        }
    }
}

// ---------------------------------------------------------------------------
// k0: conv1 + full 16-step layer-1 LIF (time-invariant drive).
// Warp = (b, l, co-chunk); lane = co. Ballot -> [t][b][l][co-words].
// ---------------------------------------------------------------------------
__global__ void k0_kernel(const float* __restrict__ x,
                          const float* __restrict__ W1,
                          const float* __restrict__ b1) {
    int gw   = blockIdx.x * (blockDim.x >> 5) + (threadIdx.x >> 5);
    int lane = threadIdx.x & 31;
    int cw = gw & 7;
    int l  = (gw >> 3) & 127;
    int b  = gw >> 10;
    int co = cw * 32 + lane;

    float cur = b1[co];
#pragma unroll
    for (int ci = 0; ci < 2; ci++) {
        const float* xr = x + ((size_t)b * 2 + ci) * Lx;
        const float* wr = W1 + (co * 2 + ci) * 5;
#pragma unroll
        for (int k = 0; k < 5; k++) {
            int ll = l + k - 2;
            float xv = (ll >= 0 && ll < Lx) ? xr[ll] : 0.0f;
            cur = fmaf(xv, wr[k], cur);
        }
    }
    float m = 0.0f;
#pragma unroll
    for (int t = 0; t < Tst; t++) {
        float r = (m > 1.0f) ? 1.0f : 0.0f;
        m = fmaf(0.9f, m, cur) - r;
        unsigned bal = __ballot_sync(0xffffffffu, m > 1.0f);
        if (lane == 0)
            g_s1[(((size_t)t * Bsz + b) * Lx + l) * 8 + cw] = bal;
    }
}

// ---------------------------------------------------------------------------
// bit-pair -> packed bf16x2 {0,1}
// ---------------------------------------------------------------------------
__device__ __forceinline__ uint32_t bits2bf(uint32_t two) {
    return ((two & 1u) ? 0x3F80u : 0u) | ((two & 2u) ? 0x3F800000u : 0u);
}

// ---------------------------------------------------------------------------
// hmmaconv<CI,CO>: K=3 pad=1 conv over binary spikes as bf16 HMMA GEMM
// with 3-split weights, fused LIF, bit-packed output.
// CTA = 1 sample, 256 thr = 8 warps, 4(M) x 2(N); warp tile 32 x CO/2.
// ---------------------------------------------------------------------------
template <int CI, int CO>
__global__ void __launch_bounds__(256, 2)
hmmaconv_kernel(int t, const uint32_t* __restrict__ sin,
                uint32_t* __restrict__ sout,
                const uint32_t* __restrict__ frag,
                const float* __restrict__ bias,
                float* __restrict__ mem) {
    constexpr int NW  = CI / 32;       // bit-words per row
    constexpr int NWP = NW + 1;        // padded smem stride
    constexpr int KT  = CI / 16;       // k16-tiles per shift
    constexpr int NT  = CO / 8;        // n8-tiles total
    constexpr int NTW = CO / 16;       // n8-tiles per warp (2 warp-cols)

    __shared__ uint32_t sbits[130 * NWP];         // shift-padded bit rows
    __shared__ uint32_t sspk[128 * CO / 4];       // spike bytes (u32-aliased)

    int tid = threadIdx.x;
    int b   = blockIdx.x;
    int wid = tid >> 5;
    int lane = tid & 31;
    int g = lane >> 2, tg = lane & 3;
    int wm = (wid >> 1) * 32;          // warp M base
    int wc = wid & 1;                  // warp N col

    // stage bit rows 1..128; rows 0 and 129 = zero (padding)
    const uint32_t* srow = sin + (size_t)b * Lx * NW;
    for (int j = tid; j < 128 * NW; j += 256) {
        int l = j / NW, w = j % NW;
        sbits[(l + 1) * NWP + w] = srow[j];
    }
    for (int j = tid; j < 2 * NWP; j += 256) {
        int r = (j < NWP) ? 0 : 129;
        sbits[r * NWP + (j % NWP)] = 0u;
    }
    __syncthreads();

    float d[2][NTW][4];
#pragma unroll
    for (int mt = 0; mt < 2; mt++)
#pragma unroll
        for (int n = 0; n < NTW; n++)
#pragma unroll
            for (int e = 0; e < 4; e++) d[mt][n][e] = 0.0f;

    const uint2* f2 = (const uint2*)frag;

#pragma unroll
    for (int k = 0; k < 3; k++) {
#pragma unroll 1
        for (int kt = 0; kt < KT; kt++) {
            int wi = kt >> 1;
            int off0 = (kt & 1) * 16 + tg * 2;
            uint32_t a[2][4];
#pragma unroll
            for (int mt = 0; mt < 2; mt++) {
                uint32_t wlo = sbits[(wm + mt * 16 + g + k) * NWP + wi];
                uint32_t whi = sbits[(wm + mt * 16 + g + 8 + k) * NWP + wi];
                a[mt][0] = bits2bf((wlo >> off0) & 3u);
                a[mt][1] = bits2bf((whi >> off0) & 3u);
                a[mt][2] = bits2bf((wlo >> (off0 + 8)) & 3u);
                a[mt][3] = bits2bf((whi >> (off0 + 8)) & 3u);
            }
#pragma unroll
            for (int split = 0; split < 3; split++) {
                int bi = k * 3 + split;
                const uint2* bp =
                    f2 + ((size_t)(bi * KT + kt) * NT + wc * NTW) * 32 + lane;
#pragma unroll
                for (int n = 0; n < NTW; n++) {
                    uint2 bv = bp[n * 32];
#pragma unroll
                    for (int mt = 0; mt < 2; mt++) {
                        asm volatile(
                            "mma.sync.aligned.m16n8k16.row.col.f32.bf16.bf16.f32 "
                            "{%0,%1,%2,%3}, {%4,%5,%6,%7}, {%8,%9}, {%0,%1,%2,%3};"
                            : "+f"(d[mt][n][0]), "+f"(d[mt][n][1]),
                              "+f"(d[mt][n][2]), "+f"(d[mt][n][3])
                            : "r"(a[mt][0]), "r"(a[mt][1]),
                              "r"(a[mt][2]), "r"(a[mt][3]),
                              "r"(bv.x), "r"(bv.y));
                    }
                }
            }
        }
    }

    // fused LIF epilogue: owner lane updates mem, drops spike byte to smem
    uint8_t* spk8 = (uint8_t*)sspk;
    float* mb = mem + (size_t)b * Lx * CO;
#pragma unroll
    for (int mt = 0; mt < 2; mt++)
#pragma unroll
        for (int n = 0; n < NTW; n++)
#pragma unroll
            for (int e = 0; e < 4; e++) {
                int row = wm + mt * 16 + g + (e >> 1) * 8;
                int co = wc * (CO / 2) + n * 8 + tg * 2 + (e & 1);
                float cur = d[mt][n][e] + __ldg(&bias[co]);
                float m0 = (t == 0) ? 0.0f : mb[row * CO + co];
                float r = (m0 > 1.0f) ? 1.0f : 0.0f;
                float m = fmaf(0.9f, m0, cur) - r;
                mb[row * CO + co] = m;
                spk8[row * CO + co] = (m > 1.0f) ? 1 : 0;
            }
    __syncthreads();

    // pack spike bytes -> bit words [b][l][CO/32]
    constexpr int NWORDS = 128 * (CO / 32);
    uint32_t* so = sout + (size_t)b * Lx * (CO / 32);
    for (int w = tid; w < NWORDS; w += 256) {
        int row = w / (CO / 32);
        int wd = w % (CO / 32);
        const uint32_t* p = &sspk[(row * CO + wd * 32) / 4];
        uint32_t bits = 0;
#pragma unroll
        for (int jj = 0; jj < 8; jj++) {
            uint32_t v = p[jj];
            bits |= ((v >> 0) & 1u) << (jj * 4 + 0);
            bits |= ((v >> 8) & 1u) << (jj * 4 + 1);
            bits |= ((v >> 16) & 1u) << (jj * 4 + 2);
            bits |= ((v >> 24) & 1u) << (jj * 4 + 3);
        }
        so[w] = bits;
    }
}

// ---------------------------------------------------------------------------
// k45: conv4(64->2,K3)+LIF4 + fc1+LIF5 + fc2 accumulate. s3: [b][l][2 words].
// ---------------------------------------------------------------------------
__global__ void k45_kernel(int t,
                           const float* __restrict__ W4, const float* __restrict__ b4,
                           const float* __restrict__ fw1, const float* __restrict__ fb1,
                           const float* __restrict__ fw2, const float* __restrict__ fb2,
                           float* __restrict__ out) {
    __shared__ uint32_t s3w[Lx * 2];
    __shared__ float    w4s[2 * C3 * 3];
    __shared__ float    s4f[256];
    __shared__ float    s5f[100];

    int tid = threadIdx.x;
    int b   = blockIdx.x;

    for (int j = tid; j < Lx * 2; j += 128)     s3w[j] = g_s3[(size_t)b * Lx * 2 + j];
    for (int j = tid; j < 2 * C3 * 3; j += 128) w4s[j] = W4[j];
    __syncthreads();

#pragma unroll
    for (int half = 0; half < 2; half++) {
        int o  = tid + half * 128;
        int co = o >> 7;
        int l  = o & 127;
        float cur = b4[co];
#pragma unroll
        for (int dk = 0; dk < 3; dk++) {
            int ll = l + dk - 1;
            if (ll < 0 || ll >= Lx) continue;
            uint32_t w0 = s3w[ll * 2], w1 = s3w[ll * 2 + 1];
            const float* wr = &w4s[co * C3 * 3 + dk];
#pragma unroll 1
            for (int ci = 0; ci < 32; ci++)
                cur += ((w0 >> ci) & 1u) ? wr[ci * 3] : 0.0f;
#pragma unroll 1
            for (int ci = 0; ci < 32; ci++)
                cur += ((w1 >> ci) & 1u) ? wr[(32 + ci) * 3] : 0.0f;
        }
        float m = (t == 0) ? 0.0f : g_mem4[(size_t)b * 256 + o];
        float r = (m > 1.0f) ? 1.0f : 0.0f;
        m = fmaf(0.9f, m, cur) - r;
        g_mem4[(size_t)b * 256 + o] = m;
        s4f[o] = (m > 1.0f) ? 1.0f : 0.0f;
    }
    __syncthreads();

    if (tid < 100) {
        float cur = fb1[tid];
        const float* wr = fw1 + (size_t)tid * 256;
#pragma unroll 4
        for (int j = 0; j < 256; j++) cur = fmaf(s4f[j], wr[j], cur);
        float m = (t == 0) ? 0.0f : g_mem5[(size_t)b * 100 + tid];
        float r = (m > 1.0f) ? 1.0f : 0.0f;
        m = fmaf(0.9f, m, cur) - r;
        g_mem5[(size_t)b * 100 + tid] = m;
        s5f[tid] = (m > 1.0f) ? 1.0f : 0.0f;
    }
    __syncthreads();

    if (tid < 40) {
        float v = 0.0f;
        const float* wr = fw2 + (size_t)tid * 100;
#pragma unroll 4
        for (int j = 0; j < 100; j++) v = fmaf(s5f[j], wr[j], v);
        size_t oi = (size_t)b * 40 + tid;
        float sum = (t == 0) ? v : (out[oi] + v);
        out[oi] = (t == Tst - 1) ? (sum * (1.0f / Tst) + fb2[tid]) : sum;
    }
}

// ---------------------------------------------------------------------------
extern "C" void kernel_launch(void* const* d_in, const int* in_sizes, int n_in,
                              void* d_out, int out_size) {
    const float* x   = (const float*)d_in[0];
    const float* W1  = (const float*)d_in[1];
    const float* b1  = (const float*)d_in[2];
    const float* W2  = (const float*)d_in[3];
    const float* b2  = (const float*)d_in[4];
    const float* W3  = (const float*)d_in[5];
    const float* b3  = (const float*)d_in[6];
    const float* W4  = (const float*)d_in[7];
    const float* b4  = (const float*)d_in[8];
    const float* fw1 = (const float*)d_in[9];
    const float* fb1 = (const float*)d_in[10];
    const float* fw2 = (const float*)d_in[11];
    const float* fb2 = (const float*)d_in[12];
    float* out = (float*)d_out;

    void *ps1, *ps2, *ps3, *pm2, *pm3, *pf2, *pf3;
    cudaGetSymbolAddress(&ps1, g_s1);
    cudaGetSymbolAddress(&ps2, g_s2);
    cudaGetSymbolAddress(&ps3, g_s3);
    cudaGetSymbolAddress(&pm2, g_mem2);
    cudaGetSymbolAddress(&pm3, g_mem3);
    cudaGetSymbolAddress(&pf2, g_fragB2);
    cudaGetSymbolAddress(&pf3, g_fragB3);

    prep_kernel<<<(9 * 16 * 16 * 32 + 255) / 256, 256>>>(W2, W3);
    k0_kernel<<<Bsz * Lx, 256>>>(x, W1, b1);

    for (int t = 0; t < Tst; t++) {
        hmmaconv_kernel<C1, C2><<<Bsz, 256>>>(
            t, (const uint32_t*)ps1 + (size_t)t * Bsz * Lx * 8,
            (uint32_t*)ps2, (const uint32_t*)pf2, b2, (float*)pm2);
        hmmaconv_kernel<C2, C3><<<Bsz, 256>>>(
            t, (const uint32_t*)ps2,
            (uint32_t*)ps3, (const uint32_t*)pf3, b3, (float*)pm3);
        k45_kernel<<<Bsz, 128>>>(t, W4, b4, fw1, fb1, fw2, fb2, out);
    }
}